// round 5
// baseline (speedup 1.0000x reference)
#include <cuda_runtime.h>

#define NQ     1224
#define TWOQ   2448
#define SMAX   50
#define SM1    (SMAX - 1)
#define ROWS   (1024 * SM1)            // 50176 (b, t) pairs, t = 1..49
#define VEC4   (TWOQ / 4)              // 612 float4 per batch row
#define WPB    2                       // 2 warps per CTA: fine-grain retirement
#define THREADS (WPB * 32)
#define BLOCKS  (ROWS / WPB)           // 25088
#define FULLM  0xffffffffu

__global__ void init_out_kernel(float* out) {
    if (threadIdx.x == 0) out[0] = 0.0f;
}

__device__ __forceinline__ unsigned nz4(const float4& v) {
    return __float_as_uint(v.x) | __float_as_uint(v.y) |
           __float_as_uint(v.z) | __float_as_uint(v.w);
}

__device__ __forceinline__ int locate4(const float4& v, int i) {
    int base = i * 4;
    if (v.x != 0.0f) return base;
    if (v.y != 0.0f) return base + 1;
    if (v.z != 0.0f) return base + 2;
    return base + 3;
}

__global__ __launch_bounds__(THREADS)
void loss_kernel(const float* __restrict__ pred,
                 const float* __restrict__ batch,
                 float* __restrict__ out) {
    const int wid  = threadIdx.x >> 5;
    const int lane = threadIdx.x & 31;
    const int row  = blockIdx.x * WPB + wid;       // 0..50175

    const int b = row / SM1;
    const int t = row - b * SM1 + 1;               // 1..49 (delta step)
    const float4* __restrict__ rp =
        (const float4*)(batch + ((size_t)b * SMAX + t) * TWOQ);

    // Scan the 2448-col row for the single nonzero (one-hot).
    // 4 LDG.128 per lane per iteration (2 KB/warp in flight),
    // warp-uniform early exit, cheap integer-OR nonzero test.
    int loc = -1;
    #pragma unroll 1
    for (int c = 0; c < VEC4; c += 128) {
        const int i0 = c + lane;        // max 543  < 612
        const int i1 = i0 + 32;         // max 575  < 612
        const int i2 = i0 + 64;         // max 607  < 612
        const int i3 = i0 + 96;         // max 639 -> guard
        const float4 z = make_float4(0.f, 0.f, 0.f, 0.f);
        float4 v0 = rp[i0];
        float4 v1 = rp[i1];
        float4 v2 = rp[i2];
        float4 v3 = (i3 < VEC4) ? rp[i3] : z;

        const unsigned a0 = nz4(v0);
        const unsigned a1 = nz4(v1);
        const unsigned a2 = nz4(v2);
        const unsigned a3 = nz4(v3);

        if (__ballot_sync(FULLM, a0 | a1 | a2 | a3)) {
            if      (a0) loc = locate4(v0, i0);
            else if (a1) loc = locate4(v1, i1);
            else if (a2) loc = locate4(v2, i2);
            else if (a3) loc = locate4(v3, i3);
            break;
        }
    }

    const int j = __reduce_max_sync(FULLM, loc);

    // Per-warp epilogue: single gather + log + fire-and-forget red-op.
    if (lane == 0 && j >= 0) {
        const int  q = (j < NQ) ? j : (j - NQ);
        const float p =
            __ldg(&pred[((size_t)b * SMAX + (t - 1)) * NQ + q]);
        if (p > 0.0f) {
            const float x = (j < NQ) ? p : (1.0f - p);
            atomicAdd(out, -__logf(x));
        }
    }
}

extern "C" void kernel_launch(void* const* d_in, const int* in_sizes, int n_in,
                              void* d_out, int out_size) {
    const float* pred  = (const float*)d_in[0];
    const float* batch = (const float*)d_in[1];
    float* out = (float*)d_out;

    init_out_kernel<<<1, 32>>>(out);
    loss_kernel<<<BLOCKS, THREADS>>>(pred, batch, out);
}

// round 6
// speedup vs baseline: 2.0674x; 2.0674x over previous
#include <cuda_runtime.h>

#define NQ     1224
#define TWOQ   2448
#define SMAX   50
#define SM1    (SMAX - 1)
#define ROWS   (1024 * SM1)            // 50176
#define VEC4   (TWOQ / 4)              // 612 float4 per batch row
#define ROW4   VEC4                    // float4 per row
#define WPB    8
#define THREADS 256
#define BLOCKS (ROWS / (WPB * 2))      // 3136 (2 rows per warp)
#define FULLM  0xffffffffu

__global__ void init_out_kernel(float* out) {
    if (threadIdx.x == 0) out[0] = 0.0f;
}

__device__ __forceinline__ unsigned nz4(const float4& v) {
    return __float_as_uint(v.x) | __float_as_uint(v.y) |
           __float_as_uint(v.z) | __float_as_uint(v.w);
}

__device__ __forceinline__ int locate4(const float4& v, int i) {
    int base = i * 4;
    if (v.x != 0.0f) return base;
    if (v.y != 0.0f) return base + 1;
    if (v.z != 0.0f) return base + 2;
    return base + 3;
}

// position within the (v0 @ i0, v1 @ i0+32) pair; caller guarantees nonzero
__device__ __forceinline__ int locate_pair(const float4& v0, const float4& v1,
                                           int i0) {
    return nz4(v0) ? locate4(v0, i0) : locate4(v1, i0 + 32);
}

__global__ __launch_bounds__(THREADS, 8)
void loss_kernel(const float* __restrict__ pred,
                 const float* __restrict__ batch,
                 float* __restrict__ out) {
    __shared__ float warp_part[WPB];

    const int wid  = threadIdx.x >> 5;
    const int lane = threadIdx.x & 31;
    const int gw   = blockIdx.x * WPB + wid;       // 0..25087

    const int rowA = gw * 2;
    const int rowB = rowA + 1;

    const int bA = rowA / SM1, tA = rowA - bA * SM1 + 1;   // 1..49
    const int bB = rowB / SM1, tB = rowB - bB * SM1 + 1;

    // 32-bit float4 offsets (max 31.3M < 2^31) — warp-uniform, UR-promotable
    const float4* __restrict__ batch4 = (const float4*)batch;
    const int offA = (bA * SMAX + tA) * ROW4;
    const int offB = (bB * SMAX + tB) * ROW4;

    const float4 z = make_float4(0.f, 0.f, 0.f, 0.f);

    int jA = -1, jB = -1;
    int c = 0;

    // Phase 1: scan both rows in lockstep. 4 LDG.128 per lane per iter
    // (2 KB/warp in flight), detection granularity 256 floats/row,
    // ONE ballot on the common path.
    #pragma unroll 1
    for (; c < VEC4; c += 64) {
        const int i0 = c + lane;            // max 607 < 612
        const int i1 = i0 + 32;             // max 639 -> guard
        const bool g = (i1 < VEC4);
        float4 a0 = batch4[offA + i0];
        float4 b0 = batch4[offB + i0];
        float4 a1 = g ? batch4[offA + i1] : z;
        float4 b1 = g ? batch4[offB + i1] : z;

        const unsigned na = nz4(a0) | nz4(a1);
        const unsigned nb = nz4(b0) | nz4(b1);

        if (__ballot_sync(FULLM, na | nb)) {
            const unsigned wa = __ballot_sync(FULLM, na != 0);
            const unsigned wb = __ballot_sync(FULLM, nb != 0);
            if (wa) {
                const int loc = na ? locate_pair(a0, a1, i0) : -1;
                jA = __reduce_max_sync(FULLM, loc);
            }
            if (wb) {
                const int loc = nb ? locate_pair(b0, b1, i0) : -1;
                jB = __reduce_max_sync(FULLM, loc);
            }
            c += 64;
            break;
        }
    }

    // Phase 2: finish whichever stream is still unresolved.
    if (jA < 0) {
        #pragma unroll 1
        for (int cc = c; cc < VEC4; cc += 64) {
            const int i0 = cc + lane;
            const int i1 = i0 + 32;
            float4 a0 = batch4[offA + i0];
            float4 a1 = (i1 < VEC4) ? batch4[offA + i1] : z;
            const unsigned na = nz4(a0) | nz4(a1);
            if (__ballot_sync(FULLM, na)) {
                const int loc = na ? locate_pair(a0, a1, i0) : -1;
                jA = __reduce_max_sync(FULLM, loc);
                break;
            }
        }
    }
    if (jB < 0) {
        #pragma unroll 1
        for (int cc = c; cc < VEC4; cc += 64) {
            const int i0 = cc + lane;
            const int i1 = i0 + 32;
            float4 b0 = batch4[offB + i0];
            float4 b1 = (i1 < VEC4) ? batch4[offB + i1] : z;
            const unsigned nb = nz4(b0) | nz4(b1);
            if (__ballot_sync(FULLM, nb)) {
                const int loc = nb ? locate_pair(b0, b1, i0) : -1;
                jB = __reduce_max_sync(FULLM, loc);
                break;
            }
        }
    }

    // Epilogue (lane 0): both pred gathers issued back-to-back, then logs.
    if (lane == 0) {
        float contrib = 0.0f;
        const int pA_off = (bA * SMAX + (tA - 1)) * NQ;
        const int pB_off = (bB * SMAX + (tB - 1)) * NQ;
        float pA = 0.0f, pB = 0.0f;
        if (jA >= 0)
            pA = __ldg(pred + pA_off + ((jA < NQ) ? jA : (jA - NQ)));
        if (jB >= 0)
            pB = __ldg(pred + pB_off + ((jB < NQ) ? jB : (jB - NQ)));
        if (jA >= 0 && pA > 0.0f)
            contrib -= __logf((jA < NQ) ? pA : (1.0f - pA));
        if (jB >= 0 && pB > 0.0f)
            contrib -= __logf((jB < NQ) ? pB : (1.0f - pB));
        warp_part[wid] = contrib;
    }
    __syncthreads();

    // One atomic per block (3136 total) — same-address L2 serialization
    // stays invisible (per-warp atomics cost ~100us, see R5).
    if (threadIdx.x == 0) {
        float s = 0.0f;
        #pragma unroll
        for (int w = 0; w < WPB; ++w) s += warp_part[w];
        atomicAdd(out, s);
    }
}

extern "C" void kernel_launch(void* const* d_in, const int* in_sizes, int n_in,
                              void* d_out, int out_size) {
    const float* pred  = (const float*)d_in[0];
    const float* batch = (const float*)d_in[1];
    float* out = (float*)d_out;

    init_out_kernel<<<1, 32>>>(out);
    loss_kernel<<<BLOCKS, THREADS>>>(pred, batch, out);
}